// round 2
// baseline (speedup 1.0000x reference)
#include <cuda_runtime.h>

#define N_NODES 50000
#define N_EDGES 800000

// ---------------- scratch (module globals; no runtime allocation) ----------------
__device__ int   g_deg[N_NODES];
__device__ int   g_off[N_NODES];
__device__ int   g_cur[N_NODES];
__device__ int   g_srcidx[N_EDGES];
__device__ __align__(16) float g_agg48[N_NODES * 48];  // [n][48]: x-sum(16) then c-sum(32, sample-major)
__device__ float g_s1[2][64];                          // per-path per-col sum of pre-BN z
__device__ float g_s2[2][64];                          // per-path per-col sum of z^2
__device__ float g_W1f[2][24 * 64];                    // BN-folded W1 (0=shared,1=agg)
__device__ float g_b1f[2][64];

// ---------------- packed f32x2 helpers (Blackwell FFMA2) ----------------
typedef unsigned long long u64;
__device__ __forceinline__ u64 dup2(float v) {
    u64 r; asm("mov.b64 %0, {%1,%1};" : "=l"(r) : "f"(v)); return r;
}
__device__ __forceinline__ void fma2(u64 &d, u64 a, u64 b) {
    asm("fma.rn.f32x2 %0, %1, %2, %3;" : "=l"(d) : "l"(a), "l"(b), "l"(d));
}
__device__ __forceinline__ void unpack2(u64 v, float &lo, float &hi) {
    asm("mov.b64 {%0,%1}, %2;" : "=f"(lo), "=f"(hi) : "l"(v));
}

// ================= K0: zero degree counters + stat accumulators ==================
__global__ void k_zero() {
    int tid = blockIdx.x * blockDim.x + threadIdx.x;
    if (tid < N_NODES) g_deg[tid] = 0;
    if (tid < 128) { ((float*)g_s1)[tid] = 0.f; ((float*)g_s2)[tid] = 0.f; }
}

// ================= K1: histogram of dst ==========================================
__global__ void k_hist(const int* __restrict__ ei) {
    int e = blockIdx.x * blockDim.x + threadIdx.x;
    if (e < N_EDGES) atomicAdd(&g_deg[ei[N_EDGES + e]], 1);
}

// ================= K2: single-block exclusive scan -> offsets ====================
__global__ void __launch_bounds__(1024) k_scan() {
    __shared__ int sm[1024];
    int t = threadIdx.x;
    int base = t * 49;
    int run = 0;
#pragma unroll 1
    for (int i = 0; i < 49; i++) {
        int idx = base + i;
        if (idx < N_NODES) run += g_deg[idx];
    }
    sm[t] = run;
    __syncthreads();
    for (int ofs = 1; ofs < 1024; ofs <<= 1) {
        int v = (t >= ofs) ? sm[t - ofs] : 0;
        __syncthreads();
        sm[t] += v;
        __syncthreads();
    }
    run = (t == 0) ? 0 : sm[t - 1];
#pragma unroll 1
    for (int i = 0; i < 49; i++) {
        int idx = base + i;
        if (idx < N_NODES) {
            int d = g_deg[idx];
            g_off[idx] = run;
            g_cur[idx] = run;
            run += d;
        }
    }
}

// ================= K3: bucket-fill src indices by dst ============================
__global__ void k_bucket(const int* __restrict__ ei) {
    int e = blockIdx.x * blockDim.x + threadIdx.x;
    if (e >= N_EDGES) return;
    int d = ei[N_EDGES + e];
    int s = ei[e];
    int p = atomicAdd(&g_cur[d], 1);
    g_srcidx[p] = s;
}

// ================= K4: CSR gather (sum neighbour features, 48 floats/node) ======
__global__ void __launch_bounds__(256) k_gather(const float* __restrict__ x,
                                                const float* __restrict__ c) {
    int n = blockIdx.x * 64 + (threadIdx.x >> 2);
    int q = threadIdx.x & 3;
    if (n >= N_NODES) return;
    int start = g_off[n], deg = g_deg[n];
    float4 a0 = make_float4(0.f, 0.f, 0.f, 0.f);
    float4 a1 = a0, a2 = a0;
    const float4* x4 = reinterpret_cast<const float4*>(x);
    const float4* c4 = reinterpret_cast<const float4*>(c);
    for (int i = 0; i < deg; i++) {
        int s = __ldg(&g_srcidx[start + i]);
        float4 vx = __ldg(&x4[s * 4 + q]);
        float4 vc0 = __ldg(&c4[s * 8 + q]);
        float4 vc1 = __ldg(&c4[s * 8 + 4 + q]);
        a0.x += vx.x;  a0.y += vx.y;  a0.z += vx.z;  a0.w += vx.w;
        a1.x += vc0.x; a1.y += vc0.y; a1.z += vc0.z; a1.w += vc0.w;
        a2.x += vc1.x; a2.y += vc1.y; a2.z += vc1.z; a2.w += vc1.w;
    }
    float4* out = reinterpret_cast<float4*>(g_agg48) + n * 12;
    out[q]     = a0;
    out[4 + q] = a1;
    out[8 + q] = a2;
}

// ================= K5: BN moment stats (sum, sumsq of pre-BN z, both paths) ======
__global__ void __launch_bounds__(256) k_stats(const float* __restrict__ x,
                                               const float* __restrict__ c,
                                               const float* __restrict__ W1s,
                                               const float* __restrict__ b1s,
                                               const float* __restrict__ W1a,
                                               const float* __restrict__ b1a,
                                               const float* __restrict__ eps_s_p,
                                               const float* __restrict__ eps_a_p) {
    __shared__ u64 w1p[2][24][32];
    __shared__ u64 b1p[2][32];
    __shared__ float mrow[8][24];
    int tid = threadIdx.x;
    for (int i = tid; i < 24 * 64; i += 256) {
        int j = i >> 6, l = i & 63;
        ((float*)&w1p[0][j][l & 31])[l >> 5] = W1s[i];
        ((float*)&w1p[1][j][l & 31])[l >> 5] = W1a[i];
    }
    if (tid < 64) {
        ((float*)&b1p[0][tid & 31])[tid >> 5] = b1s[tid];
        ((float*)&b1p[1][tid & 31])[tid >> 5] = b1a[tid];
    }
    float es = 1.f + __ldg(eps_s_p);
    float ea = 1.f + __ldg(eps_a_p);
    __syncthreads();
    int w = tid >> 5, lane = tid & 31;
    float s_lo[2] = {0.f, 0.f}, s_hi[2] = {0.f, 0.f};
    float q_lo[2] = {0.f, 0.f}, q_hi[2] = {0.f, 0.f};
    int gw = blockIdx.x * 8 + w, nw = gridDim.x * 8;
    for (int r = gw; r < 250000; r += nw) {
        int path = (r >= 200000) ? 1 : 0;
        __syncwarp();
        if (lane < 24) {
            float v;
            if (!path) {
                int n = r >> 2, s = r & 3;
                if (lane < 16)
                    v = es * x[n * 16 + lane] + g_agg48[n * 48 + lane];
                else {
                    int jj = lane - 16;
                    v = es * c[n * 32 + s * 8 + jj] + g_agg48[n * 48 + 16 + s * 8 + jj];
                }
            } else {
                int n = r - 200000;
                if (lane < 16)
                    v = ea * x[n * 16 + lane] + g_agg48[n * 48 + lane];
                else {
                    int jj = lane - 16;
                    float cm = 0.f, am = 0.f;
#pragma unroll
                    for (int s = 0; s < 4; s++) {
                        cm += c[n * 32 + s * 8 + jj];
                        am += g_agg48[n * 48 + 16 + s * 8 + jj];
                    }
                    v = ea * 0.25f * cm + 0.25f * am;
                }
            }
            mrow[w][lane] = v;
        }
        __syncwarp();
        u64 acc = b1p[path][lane];
#pragma unroll
        for (int j = 0; j < 24; j++) fma2(acc, w1p[path][j][lane], dup2(mrow[w][j]));
        float lo, hi; unpack2(acc, lo, hi);
        s_lo[path] += lo;       s_hi[path] += hi;
        q_lo[path] += lo * lo;  q_hi[path] += hi * hi;
    }
#pragma unroll
    for (int p = 0; p < 2; p++) {
        atomicAdd(&g_s1[p][lane],      s_lo[p]);
        atomicAdd(&g_s1[p][lane + 32], s_hi[p]);
        atomicAdd(&g_s2[p][lane],      q_lo[p]);
        atomicAdd(&g_s2[p][lane + 32], q_hi[p]);
    }
}

// ================= K6: fold BN into W1/b1 ========================================
__global__ void k_fold(const float* __restrict__ W1s, const float* __restrict__ b1s,
                       const float* __restrict__ g1s, const float* __restrict__ be1s,
                       const float* __restrict__ W1a, const float* __restrict__ b1a,
                       const float* __restrict__ g1a, const float* __restrict__ be1a) {
    int t = threadIdx.x;
    if (t >= 128) return;
    int path = t >> 6, cc = t & 63;
    const float* W1 = path ? W1a : W1s;
    const float* b1 = path ? b1a : b1s;
    const float* g1 = path ? g1a : g1s;
    const float* be = path ? be1a : be1s;
    float invR = path ? (1.f / 50000.f) : (1.f / 200000.f);
    float mu  = g_s1[path][cc] * invR;
    float var = g_s2[path][cc] * invR - mu * mu;
    float alpha = g1[cc] * rsqrtf(var + 1e-5f);
#pragma unroll
    for (int j = 0; j < 24; j++) g_W1f[path][j * 64 + cc] = W1[j * 64 + cc] * alpha;
    g_b1f[path][cc] = alpha * (b1[cc] - mu) + be[cc];
}

// ================= K7: fused MLPs (agg path + 4 shared samples) + DSS out ========
__global__ void __launch_bounds__(256) k_out(const float* __restrict__ x,
                                             const float* __restrict__ c,
                                             const float* __restrict__ W2s,
                                             const float* __restrict__ b2s,
                                             const float* __restrict__ W2a,
                                             const float* __restrict__ b2a,
                                             const float* __restrict__ eps_s_p,
                                             const float* __restrict__ eps_a_p,
                                             float* __restrict__ out) {
    __shared__ u64 w1s_[24][32], w1a_[24][32];
    __shared__ u64 w2s_[64][32], w2a_[64][32];
    __shared__ u64 b1s_[32], b1a_[32], b2s_[32], b2a_[32];
    __shared__ float rows[8][4][24];
    __shared__ float arow[8][24];
    __shared__ float hsm[8][64];
    int tid = threadIdx.x;
    for (int i = tid; i < 24 * 64; i += 256) {
        int j = i >> 6, l = i & 63;
        ((float*)&w1s_[j][l & 31])[l >> 5] = g_W1f[0][i];
        ((float*)&w1a_[j][l & 31])[l >> 5] = g_W1f[1][i];
    }
    for (int i = tid; i < 64 * 64; i += 256) {
        int k = i >> 6, l = i & 63;
        ((float*)&w2s_[k][l & 31])[l >> 5] = W2s[i];
        ((float*)&w2a_[k][l & 31])[l >> 5] = W2a[i];
    }
    if (tid < 64) {
        ((float*)&b1s_[tid & 31])[tid >> 5] = g_b1f[0][tid];
        ((float*)&b1a_[tid & 31])[tid >> 5] = g_b1f[1][tid];
        ((float*)&b2s_[tid & 31])[tid >> 5] = b2s[tid];
        ((float*)&b2a_[tid & 31])[tid >> 5] = b2a[tid];
    }
    float es = 1.f + __ldg(eps_s_p);
    float ea = 1.f + __ldg(eps_a_p);
    __syncthreads();
    int w = tid >> 5, lane = tid & 31;
    for (int n = blockIdx.x * 8 + w; n < N_NODES; n += gridDim.x * 8) {
        __syncwarp();
        if (lane < 24) {
            if (lane < 16) {
                float xv = x[n * 16 + lane];
                float gv = g_agg48[n * 48 + lane];
                float ms = es * xv + gv;
                rows[w][0][lane] = ms; rows[w][1][lane] = ms;
                rows[w][2][lane] = ms; rows[w][3][lane] = ms;
                arow[w][lane] = ea * xv + gv;
            } else {
                int jj = lane - 16;
                float cm = 0.f, am = 0.f;
#pragma unroll
                for (int s = 0; s < 4; s++) {
                    float cv = c[n * 32 + s * 8 + jj];
                    float av = g_agg48[n * 48 + 16 + s * 8 + jj];
                    rows[w][s][lane] = es * cv + av;
                    cm += cv; am += av;
                }
                arow[w][lane] = ea * 0.25f * cm + 0.25f * am;
            }
        }
        __syncwarp();
        // ---- aggregated path MLP (folded BN) ----
        u64 acc = b1a_[lane];
#pragma unroll
        for (int j = 0; j < 24; j++) fma2(acc, w1a_[j][lane], dup2(arow[w][j]));
        float lo, hi; unpack2(acc, lo, hi);
        hsm[w][lane]      = fmaxf(lo, 0.f);
        hsm[w][lane + 32] = fmaxf(hi, 0.f);
        __syncwarp();
        u64 o = b2a_[lane];
#pragma unroll
        for (int k = 0; k < 64; k++) fma2(o, w2a_[k][lane], dup2(hsm[w][k]));
        float malo, mahi; unpack2(o, malo, mahi);
        // ---- shared path MLP per sample + DSS combine ----
#pragma unroll
        for (int s = 0; s < 4; s++) {
            u64 a1 = b1s_[lane];
#pragma unroll
            for (int j = 0; j < 24; j++) fma2(a1, w1s_[j][lane], dup2(rows[w][s][j]));
            unpack2(a1, lo, hi);
            __syncwarp();
            hsm[w][lane]      = fmaxf(lo, 0.f);
            hsm[w][lane + 32] = fmaxf(hi, 0.f);
            __syncwarp();
            u64 o2 = b2s_[lane];
#pragma unroll
            for (int k = 0; k < 64; k++) fma2(o2, w2s_[k][lane], dup2(hsm[w][k]));
            unpack2(o2, lo, hi);
            out[n * 256 + s * 64 + lane]      = lo + malo;
            out[n * 256 + s * 64 + lane + 32] = hi + mahi;
        }
    }
}

// ================= launch ========================================================
extern "C" void kernel_launch(void* const* d_in, const int* in_sizes, int n_in,
                              void* d_out, int out_size) {
    const float* x     = (const float*)d_in[0];
    const float* c     = (const float*)d_in[1];
    const int*   ei    = (const int*)  d_in[2];
    const float* eps_s = (const float*)d_in[3];
    const float* W1s   = (const float*)d_in[4];
    const float* b1s   = (const float*)d_in[5];
    const float* g1s   = (const float*)d_in[6];
    const float* be1s  = (const float*)d_in[7];
    const float* W2s   = (const float*)d_in[8];
    const float* b2s   = (const float*)d_in[9];
    const float* eps_a = (const float*)d_in[10];
    const float* W1a   = (const float*)d_in[11];
    const float* b1a   = (const float*)d_in[12];
    const float* g1a   = (const float*)d_in[13];
    const float* be1a  = (const float*)d_in[14];
    const float* W2a   = (const float*)d_in[15];
    const float* b2a   = (const float*)d_in[16];
    float* out = (float*)d_out;

    k_zero  <<<(N_NODES + 255) / 256, 256>>>();
    k_hist  <<<(N_EDGES + 255) / 256, 256>>>(ei);
    k_scan  <<<1, 1024>>>();
    k_bucket<<<(N_EDGES + 255) / 256, 256>>>(ei);
    k_gather<<<(N_NODES + 63) / 64, 256>>>(x, c);
    k_stats <<<296, 256>>>(x, c, W1s, b1s, W1a, b1a, eps_s, eps_a);
    k_fold  <<<1, 128>>>(W1s, b1s, g1s, be1s, W1a, b1a, g1a, be1a);
    k_out   <<<592, 256>>>(x, c, W2s, b2s, W2a, b2a, eps_s, eps_a, out);
}

// round 3
// speedup vs baseline: 1.1521x; 1.1521x over previous
#include <cuda_runtime.h>

#define N_NODES 50000
#define N_EDGES 800000
#define NB 196            // ceil(N_NODES/256)

// ---------------- scratch (module globals; no runtime allocation) ----------------
__device__ int   g_deg[N_NODES];
__device__ int   g_off[N_NODES];
__device__ int   g_cur[N_NODES];
__device__ int   g_bsum[256];
__device__ int   g_boff[256];
__device__ int   g_srcidx[N_EDGES];
__device__ __align__(16) float g_agg48[N_NODES * 48];  // [n][48]: x-sum(16), c-sum(32)
__device__ float g_s1[2][64];
__device__ float g_s2[2][64];
__device__ __align__(16) float g_W1f[2][24 * 64];      // BN-folded W1 (0=shared,1=agg)
__device__ __align__(16) float g_b1f[2][64];
__device__ __align__(16) float g_ma[N_NODES * 64];     // aggregated-path output

// ---------------- packed f32x2 helpers ----------------
typedef unsigned long long u64;
__device__ __forceinline__ u64 dup2(float v) {
    u64 r; asm("mov.b64 %0, {%1,%1};" : "=l"(r) : "f"(v)); return r;
}
__device__ __forceinline__ u64 pack2(float lo, float hi) {
    u64 r; asm("mov.b64 %0, {%1,%2};" : "=l"(r) : "f"(lo), "f"(hi)); return r;
}
__device__ __forceinline__ void fma2(u64 &d, u64 a, u64 b) {
    asm("fma.rn.f32x2 %0, %1, %2, %3;" : "=l"(d) : "l"(a), "l"(b), "l"(d));
}
__device__ __forceinline__ void unpack2(u64 v, float &lo, float &hi) {
    asm("mov.b64 {%0,%1}, %2;" : "=f"(lo), "=f"(hi) : "l"(v));
}
__device__ __forceinline__ void lds_v2u64(u64 &a, u64 &b, const void* p) {
    unsigned sa = (unsigned)__cvta_generic_to_shared(p);
    asm("ld.shared.v2.u64 {%0, %1}, [%2];" : "=l"(a), "=l"(b) : "r"(sa));
}

// ================= K0: zero counters =============================================
__global__ void k_zero() {
    int tid = blockIdx.x * blockDim.x + threadIdx.x;
    if (tid < N_NODES) g_deg[tid] = 0;
    if (tid < 128) { ((float*)g_s1)[tid] = 0.f; ((float*)g_s2)[tid] = 0.f; }
}

// ================= K1: histogram of dst ==========================================
__global__ void k_hist(const int* __restrict__ ei) {
    int e = blockIdx.x * blockDim.x + threadIdx.x;
    if (e < N_EDGES) atomicAdd(&g_deg[ei[N_EDGES + e]], 1);
}

// ================= K2a: per-block degree sums ====================================
__global__ void __launch_bounds__(256) k_blksum() {
    __shared__ int sm[8];
    int t = threadIdx.x;
    int idx = blockIdx.x * 256 + t;
    int v = (idx < N_NODES) ? g_deg[idx] : 0;
#pragma unroll
    for (int o = 16; o > 0; o >>= 1) v += __shfl_down_sync(0xffffffffu, v, o);
    if ((t & 31) == 0) sm[t >> 5] = v;
    __syncthreads();
    if (t == 0) {
        int s = 0;
#pragma unroll
        for (int i = 0; i < 8; i++) s += sm[i];
        g_bsum[blockIdx.x] = s;
    }
}

// ================= K2b: scan block sums ==========================================
__global__ void __launch_bounds__(256) k_scanblk() {
    __shared__ int sm[256];
    int t = threadIdx.x;
    int v = (t < NB) ? g_bsum[t] : 0;
    sm[t] = v;
    __syncthreads();
    for (int o = 1; o < 256; o <<= 1) {
        int u = (t >= o) ? sm[t - o] : 0;
        __syncthreads();
        sm[t] += u;
        __syncthreads();
    }
    g_boff[t] = sm[t] - v;
}

// ================= K2c: per-node exclusive offsets ===============================
__global__ void __launch_bounds__(256) k_off() {
    __shared__ int sm[256];
    int t = threadIdx.x;
    int idx = blockIdx.x * 256 + t;
    int d = (idx < N_NODES) ? g_deg[idx] : 0;
    sm[t] = d;
    __syncthreads();
    for (int o = 1; o < 256; o <<= 1) {
        int u = (t >= o) ? sm[t - o] : 0;
        __syncthreads();
        sm[t] += u;
        __syncthreads();
    }
    if (idx < N_NODES) {
        int e = sm[t] - d + g_boff[blockIdx.x];
        g_off[idx] = e;
        g_cur[idx] = e;
    }
}

// ================= K3: bucket-fill src indices by dst ============================
__global__ void k_bucket(const int* __restrict__ ei) {
    int e = blockIdx.x * blockDim.x + threadIdx.x;
    if (e >= N_EDGES) return;
    int d = ei[N_EDGES + e];
    int s = ei[e];
    int p = atomicAdd(&g_cur[d], 1);
    g_srcidx[p] = s;
}

// ================= K4: CSR gather (sum neighbour features) ======================
__global__ void __launch_bounds__(256) k_gather(const float* __restrict__ x,
                                                const float* __restrict__ c) {
    int n = blockIdx.x * 64 + (threadIdx.x >> 2);
    int q = threadIdx.x & 3;
    if (n >= N_NODES) return;
    int start = g_off[n], deg = g_deg[n];
    float4 a0 = make_float4(0.f, 0.f, 0.f, 0.f);
    float4 a1 = a0, a2 = a0;
    const float4* x4 = reinterpret_cast<const float4*>(x);
    const float4* c4 = reinterpret_cast<const float4*>(c);
    int i = 0;
    for (; i + 2 <= deg; i += 2) {
        int s0 = __ldg(&g_srcidx[start + i]);
        int s1 = __ldg(&g_srcidx[start + i + 1]);
        float4 vx0 = __ldg(&x4[s0 * 4 + q]);
        float4 vc00 = __ldg(&c4[s0 * 8 + q]);
        float4 vc01 = __ldg(&c4[s0 * 8 + 4 + q]);
        float4 vx1 = __ldg(&x4[s1 * 4 + q]);
        float4 vc10 = __ldg(&c4[s1 * 8 + q]);
        float4 vc11 = __ldg(&c4[s1 * 8 + 4 + q]);
        a0.x += vx0.x + vx1.x;   a0.y += vx0.y + vx1.y;
        a0.z += vx0.z + vx1.z;   a0.w += vx0.w + vx1.w;
        a1.x += vc00.x + vc10.x; a1.y += vc00.y + vc10.y;
        a1.z += vc00.z + vc10.z; a1.w += vc00.w + vc10.w;
        a2.x += vc01.x + vc11.x; a2.y += vc01.y + vc11.y;
        a2.z += vc01.z + vc11.z; a2.w += vc01.w + vc11.w;
    }
    if (i < deg) {
        int s0 = __ldg(&g_srcidx[start + i]);
        float4 vx = __ldg(&x4[s0 * 4 + q]);
        float4 vc0 = __ldg(&c4[s0 * 8 + q]);
        float4 vc1 = __ldg(&c4[s0 * 8 + 4 + q]);
        a0.x += vx.x;  a0.y += vx.y;  a0.z += vx.z;  a0.w += vx.w;
        a1.x += vc0.x; a1.y += vc0.y; a1.z += vc0.z; a1.w += vc0.w;
        a2.x += vc1.x; a2.y += vc1.y; a2.z += vc1.z; a2.w += vc1.w;
    }
    float4* out = reinterpret_cast<float4*>(g_agg48) + n * 12;
    out[q]     = a0;
    out[4 + q] = a1;
    out[8 + q] = a2;
}

// ================= K5: BN moment stats (register-blocked layer-1 pass) ==========
__global__ void __launch_bounds__(256) k_stats(const float* __restrict__ x,
                                               const float* __restrict__ c,
                                               const float* __restrict__ W1s,
                                               const float* __restrict__ b1s,
                                               const float* __restrict__ W1a,
                                               const float* __restrict__ b1a,
                                               const float* __restrict__ eps_s_p,
                                               const float* __restrict__ eps_a_p) {
    __shared__ float4 w1qs[24][16], w1qa[24][16];
    __shared__ float4 b1qs[16], b1qa[16];
    __shared__ float rows[8][2][24];
    int tid = threadIdx.x;
    for (int i = tid; i < 24 * 16; i += 256) {
        int j = i >> 4, l = i & 15;
        w1qs[j][l] = *reinterpret_cast<const float4*>(&W1s[j * 64 + 4 * l]);
        w1qa[j][l] = *reinterpret_cast<const float4*>(&W1a[j * 64 + 4 * l]);
    }
    if (tid < 16) {
        b1qs[tid] = *reinterpret_cast<const float4*>(&b1s[4 * tid]);
        b1qa[tid] = *reinterpret_cast<const float4*>(&b1a[4 * tid]);
    }
    float es = 1.f + __ldg(eps_s_p);
    float ea = 1.f + __ldg(eps_a_p);
    __syncthreads();
    int w = tid >> 5, lane = tid & 31;
    int l16 = lane & 15, nd = lane >> 4;
    float ss[4] = {0.f,0.f,0.f,0.f}, sq[4] = {0.f,0.f,0.f,0.f};
    float as_[4] = {0.f,0.f,0.f,0.f}, aq[4] = {0.f,0.f,0.f,0.f};
    int gw = blockIdx.x * 8 + w, nwp = gridDim.x * 8;
    for (int p = gw; p < 125000; p += nwp) {
        int shp = (p < 100000);
        __syncwarp();
        // build two rows (48 values over 32 lanes, lanes 32..47 handled in iter 2)
        for (int it = 0; it < 2; it++) {
            int idx = lane + it * 32;
            if (idx < 48) {
                int node = idx / 24, j = idx % 24;
                float v;
                if (shp) {
                    int row = 2 * p + node;
                    int n = row >> 2, s = row & 3;
                    if (j < 16) v = es * x[n * 16 + j] + g_agg48[n * 48 + j];
                    else {
                        int jj = j - 16;
                        v = es * c[n * 32 + s * 8 + jj] + g_agg48[n * 48 + 16 + s * 8 + jj];
                    }
                } else {
                    int n = 2 * (p - 100000) + node;
                    if (j < 16) v = ea * x[n * 16 + j] + g_agg48[n * 48 + j];
                    else {
                        int jj = j - 16;
                        float cm = 0.f, am = 0.f;
#pragma unroll
                        for (int s = 0; s < 4; s++) {
                            cm += c[n * 32 + s * 8 + jj];
                            am += g_agg48[n * 48 + 16 + s * 8 + jj];
                        }
                        v = 0.25f * (ea * cm + am);
                    }
                }
                rows[w][node][j] = v;
            }
        }
        __syncwarp();
        float4 bq = shp ? b1qs[l16] : b1qa[l16];
        u64 acc0 = pack2(bq.x, bq.y);
        u64 acc1 = pack2(bq.z, bq.w);
        const float4 (*wq)[16] = shp ? w1qs : w1qa;
#pragma unroll
        for (int j = 0; j < 24; j++) {
            u64 w0, w1v;
            lds_v2u64(w0, w1v, &wq[j][l16]);
            u64 h = dup2(rows[w][nd][j]);
            fma2(acc0, w0, h);
            fma2(acc1, w1v, h);
        }
        float z0, z1, z2, z3;
        unpack2(acc0, z0, z1);
        unpack2(acc1, z2, z3);
        if (shp) {
            ss[0] += z0; ss[1] += z1; ss[2] += z2; ss[3] += z3;
            sq[0] += z0*z0; sq[1] += z1*z1; sq[2] += z2*z2; sq[3] += z3*z3;
        } else {
            as_[0] += z0; as_[1] += z1; as_[2] += z2; as_[3] += z3;
            aq[0] += z0*z0; aq[1] += z1*z1; aq[2] += z2*z2; aq[3] += z3*z3;
        }
    }
#pragma unroll
    for (int i = 0; i < 4; i++) {
        atomicAdd(&g_s1[0][4 * l16 + i], ss[i]);
        atomicAdd(&g_s2[0][4 * l16 + i], sq[i]);
        atomicAdd(&g_s1[1][4 * l16 + i], as_[i]);
        atomicAdd(&g_s2[1][4 * l16 + i], aq[i]);
    }
}

// ================= K6: fold BN into W1/b1 ========================================
__global__ void k_fold(const float* __restrict__ W1s, const float* __restrict__ b1s,
                       const float* __restrict__ g1s, const float* __restrict__ be1s,
                       const float* __restrict__ W1a, const float* __restrict__ b1a,
                       const float* __restrict__ g1a, const float* __restrict__ be1a) {
    int t = threadIdx.x;
    if (t >= 128) return;
    int path = t >> 6, cc = t & 63;
    const float* W1 = path ? W1a : W1s;
    const float* b1 = path ? b1a : b1s;
    const float* g1 = path ? g1a : g1s;
    const float* be = path ? be1a : be1s;
    float invR = path ? (1.f / 50000.f) : (1.f / 200000.f);
    float mu  = g_s1[path][cc] * invR;
    float var = g_s2[path][cc] * invR - mu * mu;
    float alpha = g1[cc] * rsqrtf(var + 1e-5f);
#pragma unroll
    for (int j = 0; j < 24; j++) g_W1f[path][j * 64 + cc] = W1[j * 64 + cc] * alpha;
    g_b1f[path][cc] = alpha * (b1[cc] - mu) + be[cc];
}

// ================= K7a: aggregated-path MLP -> g_ma =============================
__global__ void __launch_bounds__(256) k_agg(const float* __restrict__ x,
                                             const float* __restrict__ c,
                                             const float* __restrict__ W2a,
                                             const float* __restrict__ b2a,
                                             const float* __restrict__ eps_a_p) {
    __shared__ float4 w1q[24][16];
    __shared__ float4 w2q[64][16];
    __shared__ float4 b1q[16], b2q[16];
    __shared__ float rows[8][2][24];
    __shared__ float hsm[8][2][64];
    int tid = threadIdx.x;
    for (int i = tid; i < 24 * 16; i += 256) {
        int j = i >> 4, l = i & 15;
        w1q[j][l] = *reinterpret_cast<const float4*>(&g_W1f[1][j * 64 + 4 * l]);
    }
    for (int i = tid; i < 64 * 16; i += 256) {
        int k = i >> 4, l = i & 15;
        w2q[k][l] = *reinterpret_cast<const float4*>(&W2a[k * 64 + 4 * l]);
    }
    if (tid < 16) {
        b1q[tid] = *reinterpret_cast<const float4*>(&g_b1f[1][4 * tid]);
        b2q[tid] = *reinterpret_cast<const float4*>(&b2a[4 * tid]);
    }
    float ea = 1.f + __ldg(eps_a_p);
    __syncthreads();
    int w = tid >> 5, lane = tid & 31;
    int l16 = lane & 15, nd = lane >> 4;
    float4 b1v = b1q[l16], b2v = b2q[l16];
    u64 b1lo = pack2(b1v.x, b1v.y), b1hi = pack2(b1v.z, b1v.w);
    u64 b2lo = pack2(b2v.x, b2v.y), b2hi = pack2(b2v.z, b2v.w);
    for (int p = blockIdx.x * 8 + w; p < 25000; p += gridDim.x * 8) {
        int nA = 2 * p;
        __syncwarp();
        {
            int idx = lane;
            if (idx < 48 - 32 + 32) {}  // noop
            for (int it = 0; it < 2; it++) {
                int id2 = lane + it * 32;
                if (id2 < 48) {
                    int node = id2 / 24, j = id2 % 24;
                    int n = nA + node;
                    float v;
                    if (j < 16) v = ea * x[n * 16 + j] + g_agg48[n * 48 + j];
                    else {
                        int jj = j - 16;
                        float cm = 0.f, am = 0.f;
#pragma unroll
                        for (int s = 0; s < 4; s++) {
                            cm += c[n * 32 + s * 8 + jj];
                            am += g_agg48[n * 48 + 16 + s * 8 + jj];
                        }
                        v = 0.25f * (ea * cm + am);
                    }
                    rows[w][node][j] = v;
                }
            }
        }
        __syncwarp();
        u64 acc0 = b1lo, acc1 = b1hi;
#pragma unroll
        for (int j = 0; j < 24; j++) {
            u64 w0, w1v;
            lds_v2u64(w0, w1v, &w1q[j][l16]);
            u64 h = dup2(rows[w][nd][j]);
            fma2(acc0, w0, h);
            fma2(acc1, w1v, h);
        }
        float r0, r1, r2, r3;
        unpack2(acc0, r0, r1);
        unpack2(acc1, r2, r3);
        *reinterpret_cast<float4*>(&hsm[w][nd][4 * l16]) =
            make_float4(fmaxf(r0, 0.f), fmaxf(r1, 0.f), fmaxf(r2, 0.f), fmaxf(r3, 0.f));
        __syncwarp();
        acc0 = b2lo; acc1 = b2hi;
#pragma unroll
        for (int k = 0; k < 64; k++) {
            u64 w0, w1v;
            lds_v2u64(w0, w1v, &w2q[k][l16]);
            u64 h = dup2(hsm[w][nd][k]);
            fma2(acc0, w0, h);
            fma2(acc1, w1v, h);
        }
        unpack2(acc0, r0, r1);
        unpack2(acc1, r2, r3);
        *reinterpret_cast<float4*>(&g_ma[(nA + nd) * 64 + 4 * l16]) =
            make_float4(r0, r1, r2, r3);
    }
}

// ================= K7b: shared-path MLP + DSS combine -> out =====================
__global__ void __launch_bounds__(256) k_shared(const float* __restrict__ x,
                                                const float* __restrict__ c,
                                                const float* __restrict__ W2s,
                                                const float* __restrict__ b2s,
                                                const float* __restrict__ eps_s_p,
                                                float* __restrict__ out) {
    __shared__ float4 w1q[24][16];
    __shared__ float4 w2q[64][16];
    __shared__ float4 b1q[16], b2q[16];
    __shared__ float rows[8][2][4][24];
    __shared__ float hsm[8][2][64];
    int tid = threadIdx.x;
    for (int i = tid; i < 24 * 16; i += 256) {
        int j = i >> 4, l = i & 15;
        w1q[j][l] = *reinterpret_cast<const float4*>(&g_W1f[0][j * 64 + 4 * l]);
    }
    for (int i = tid; i < 64 * 16; i += 256) {
        int k = i >> 4, l = i & 15;
        w2q[k][l] = *reinterpret_cast<const float4*>(&W2s[k * 64 + 4 * l]);
    }
    if (tid < 16) {
        b1q[tid] = *reinterpret_cast<const float4*>(&g_b1f[0][4 * tid]);
        b2q[tid] = *reinterpret_cast<const float4*>(&b2s[4 * tid]);
    }
    float es = 1.f + __ldg(eps_s_p);
    __syncthreads();
    int w = tid >> 5, lane = tid & 31;
    int l16 = lane & 15, nd = lane >> 4;
    float4 b1v = b1q[l16], b2v = b2q[l16];
    u64 b1lo = pack2(b1v.x, b1v.y), b1hi = pack2(b1v.z, b1v.w);
    u64 b2lo = pack2(b2v.x, b2v.y), b2hi = pack2(b2v.z, b2v.w);
    for (int p = blockIdx.x * 8 + w; p < 25000; p += gridDim.x * 8) {
        int nA = 2 * p;
        int n = nA + nd;
        __syncwarp();
        // build 2 nodes x 4 sample-rows x 24 = 192 values
        for (int it = 0; it < 6; it++) {
            int idx = lane + it * 32;
            int node = idx / 96;
            int rr = (idx % 96) / 24;
            int j = idx % 24;
            int nn = nA + node;
            float v;
            if (j < 16) v = es * x[nn * 16 + j] + g_agg48[nn * 48 + j];
            else {
                int jj = j - 16;
                v = es * c[nn * 32 + rr * 8 + jj] + g_agg48[nn * 48 + 16 + rr * 8 + jj];
            }
            rows[w][node][rr][j] = v;
        }
        float4 mav = *reinterpret_cast<const float4*>(&g_ma[n * 64 + 4 * l16]);
        __syncwarp();
#pragma unroll 1
        for (int r = 0; r < 4; r++) {
            u64 acc0 = b1lo, acc1 = b1hi;
#pragma unroll
            for (int j = 0; j < 24; j++) {
                u64 w0, w1v;
                lds_v2u64(w0, w1v, &w1q[j][l16]);
                u64 h = dup2(rows[w][nd][r][j]);
                fma2(acc0, w0, h);
                fma2(acc1, w1v, h);
            }
            float r0, r1, r2, r3;
            unpack2(acc0, r0, r1);
            unpack2(acc1, r2, r3);
            __syncwarp();  // previous layer-2 reads of hsm complete
            *reinterpret_cast<float4*>(&hsm[w][nd][4 * l16]) =
                make_float4(fmaxf(r0, 0.f), fmaxf(r1, 0.f), fmaxf(r2, 0.f), fmaxf(r3, 0.f));
            __syncwarp();
            acc0 = b2lo; acc1 = b2hi;
#pragma unroll
            for (int k = 0; k < 64; k++) {
                u64 w0, w1v;
                lds_v2u64(w0, w1v, &w2q[k][l16]);
                u64 h = dup2(hsm[w][nd][k]);
                fma2(acc0, w0, h);
                fma2(acc1, w1v, h);
            }
            unpack2(acc0, r0, r1);
            unpack2(acc1, r2, r3);
            *reinterpret_cast<float4*>(&out[n * 256 + r * 64 + 4 * l16]) =
                make_float4(r0 + mav.x, r1 + mav.y, r2 + mav.z, r3 + mav.w);
        }
    }
}

// ================= launch ========================================================
extern "C" void kernel_launch(void* const* d_in, const int* in_sizes, int n_in,
                              void* d_out, int out_size) {
    const float* x     = (const float*)d_in[0];
    const float* c     = (const float*)d_in[1];
    const int*   ei    = (const int*)  d_in[2];
    const float* eps_s = (const float*)d_in[3];
    const float* W1s   = (const float*)d_in[4];
    const float* b1s   = (const float*)d_in[5];
    const float* g1s   = (const float*)d_in[6];
    const float* be1s  = (const float*)d_in[7];
    const float* W2s   = (const float*)d_in[8];
    const float* b2s   = (const float*)d_in[9];
    const float* eps_a = (const float*)d_in[10];
    const float* W1a   = (const float*)d_in[11];
    const float* b1a   = (const float*)d_in[12];
    const float* g1a   = (const float*)d_in[13];
    const float* be1a  = (const float*)d_in[14];
    const float* W2a   = (const float*)d_in[15];
    const float* b2a   = (const float*)d_in[16];
    float* out = (float*)d_out;

    k_zero   <<<NB, 256>>>();
    k_hist   <<<(N_EDGES + 255) / 256, 256>>>(ei);
    k_blksum <<<NB, 256>>>();
    k_scanblk<<<1, 256>>>();
    k_off    <<<NB, 256>>>();
    k_bucket <<<(N_EDGES + 255) / 256, 256>>>(ei);
    k_gather <<<(N_NODES + 63) / 64, 256>>>(x, c);
    k_stats  <<<296, 256>>>(x, c, W1s, b1s, W1a, b1a, eps_s, eps_a);
    k_fold   <<<1, 128>>>(W1s, b1s, g1s, be1s, W1a, b1a, g1a, be1a);
    k_agg    <<<296, 256>>>(x, c, W2a, b2a, eps_a);
    k_shared <<<592, 256>>>(x, c, W2s, b2s, eps_s, out);
}

// round 4
// speedup vs baseline: 2.6283x; 2.2812x over previous
#include <cuda_runtime.h>

#define N_NODES 50000
#define N_EDGES 800000

// ---------------- scratch ----------------
__device__ __align__(16) float g_agg48[N_NODES * 48];  // [n]: x-sum(16), c-sum(32 sample-major)
__device__ float g_s1[2][64];
__device__ float g_s2[2][64];
__device__ float g_alpha[2][64];
__device__ float g_beta[2][64];
__device__ __align__(16) float g_ma[N_NODES * 64];

// ---------------- packed f32x2 helpers ----------------
typedef unsigned long long u64;
__device__ __forceinline__ u64 dup2(float v) {
    u64 r; asm("mov.b64 %0, {%1,%1};" : "=l"(r) : "f"(v)); return r;
}
__device__ __forceinline__ u64 pack2(float lo, float hi) {
    u64 r; asm("mov.b64 %0, {%1,%2};" : "=l"(r) : "f"(lo), "f"(hi)); return r;
}
__device__ __forceinline__ void fma2(u64 &d, u64 a, u64 b) {
    asm("fma.rn.f32x2 %0, %1, %2, %3;" : "=l"(d) : "l"(a), "l"(b), "l"(d));
}
__device__ __forceinline__ void unpack2(u64 v, float &lo, float &hi) {
    asm("mov.b64 {%0,%1}, %2;" : "=f"(lo), "=f"(hi) : "l"(v));
}
__device__ __forceinline__ void lds_v2u64(u64 &a, u64 &b, const void* p) {
    unsigned sa = (unsigned)__cvta_generic_to_shared(p);
    asm("ld.shared.v2.u64 {%0, %1}, [%2];" : "=l"(a), "=l"(b) : "r"(sa));
}
__device__ __forceinline__ void red4(float4* p, float4 v) {
    asm volatile("red.global.add.v4.f32 [%0], {%1,%2,%3,%4};"
                 :: "l"(p), "f"(v.x), "f"(v.y), "f"(v.z), "f"(v.w) : "memory");
}

// ================= zero kernels (split 3-way so k_scatter is launch #4) ==========
__global__ void k_zeroA() {
    int t = blockIdx.x * 256 + threadIdx.x;
    if (t < 300000) ((float4*)g_agg48)[t] = make_float4(0.f, 0.f, 0.f, 0.f);
}
__global__ void k_zeroB() {
    int t = blockIdx.x * 256 + threadIdx.x;
    if (t < 300000) ((float4*)g_agg48)[300000 + t] = make_float4(0.f, 0.f, 0.f, 0.f);
}
__global__ void k_zeroC() {
    int t = threadIdx.x;
    if (t < 128) { ((float*)g_s1)[t] = 0.f; ((float*)g_s2)[t] = 0.f; }
}

// ================= K1: edge scatter (4 threads/edge, 3 red.v4 each) ==============
__global__ void __launch_bounds__(256) k_scatter(const int* __restrict__ ei,
                                                 const float* __restrict__ x,
                                                 const float* __restrict__ c) {
    unsigned tid = blockIdx.x * 256u + threadIdx.x;
    unsigned e = tid >> 2;
    if (e >= N_EDGES) return;
    unsigned q = tid & 3;
    int src = __ldg(ei + e);
    int dst = __ldg(ei + N_EDGES + e);
    const float4* x4 = reinterpret_cast<const float4*>(x);
    const float4* c4 = reinterpret_cast<const float4*>(c);
    float4 vx = __ldg(&x4[src * 4 + q]);
    float4 v0 = __ldg(&c4[src * 8 + q]);
    float4 v1 = __ldg(&c4[src * 8 + 4 + q]);
    float4* d = reinterpret_cast<float4*>(g_agg48) + dst * 12;
    red4(d + q, vx);
    red4(d + 4 + q, v0);
    red4(d + 8 + q, v1);
}

// ================= K2: BN moment stats (layer-1 for both paths, factored) ========
__global__ void __launch_bounds__(256) k_stats(const float* __restrict__ x,
                                               const float* __restrict__ c,
                                               const float* __restrict__ W1s,
                                               const float* __restrict__ b1s,
                                               const float* __restrict__ W1a,
                                               const float* __restrict__ b1a,
                                               const float* __restrict__ eps_s_p,
                                               const float* __restrict__ eps_a_p) {
    __shared__ float4 w1qs[24][16], w1qa[24][16];
    __shared__ float msx[8][2][16], msc[8][2][4][8];
    __shared__ float max_[8][2][16], mac[8][2][8];
    __shared__ float red[8][16][16];
    int tid = threadIdx.x;
    for (int i = tid; i < 24 * 16; i += 256) {
        int j = i >> 4, l = i & 15;
        w1qs[j][l] = *reinterpret_cast<const float4*>(&W1s[j * 64 + 4 * l]);
        w1qa[j][l] = *reinterpret_cast<const float4*>(&W1a[j * 64 + 4 * l]);
    }
    float es = 1.f + __ldg(eps_s_p);
    float ea = 1.f + __ldg(eps_a_p);
    __syncthreads();
    int w = tid >> 5, lane = tid & 31, l16 = lane & 15, nd = lane >> 4;
    float4 bs4 = __ldg(reinterpret_cast<const float4*>(b1s) + l16);
    float4 ba4 = __ldg(reinterpret_cast<const float4*>(b1a) + l16);
    u64 bs0 = pack2(bs4.x, bs4.y), bs1 = pack2(bs4.z, bs4.w);
    u64 ba0 = pack2(ba4.x, ba4.y), ba1 = pack2(ba4.z, ba4.w);
    float ss[4] = {0,0,0,0}, sq[4] = {0,0,0,0}, as_[4] = {0,0,0,0}, aq[4] = {0,0,0,0};
    for (int p = blockIdx.x * 8 + w; p < 25000; p += gridDim.x * 8) {
        int nA = 2 * p;
        __syncwarp();
#pragma unroll
        for (int it = 0; it < 4; it++) {
            int idx = lane + 32 * it;
            int node = idx >> 6, r = idx & 63, n = nA + node;
            if (r < 16) msx[w][node][r] = es * x[n * 16 + r] + g_agg48[n * 48 + r];
            else if (r < 48) {
                int s = (r - 16) >> 3, j = (r - 16) & 7;
                msc[w][node][s][j] = es * c[n * 32 + s * 8 + j] + g_agg48[n * 48 + 16 + s * 8 + j];
            } else {
                int j = r - 48;
                max_[w][node][j] = ea * x[n * 16 + j] + g_agg48[n * 48 + j];
            }
        }
        __syncwarp();
        if (lane < 16) {
            int node = lane >> 3, j = lane & 7, n = nA + node;
            float csum = c[n*32 + j] + c[n*32 + 8 + j] + c[n*32 + 16 + j] + c[n*32 + 24 + j];
            float msum = msc[w][node][0][j] + msc[w][node][1][j]
                       + msc[w][node][2][j] + msc[w][node][3][j];
            mac[w][node][j] = 0.25f * (msum + (ea - es) * csum);
        }
        __syncwarp();
        u64 zc0 = bs0, zc1 = bs1, za0 = ba0, za1 = ba1;
#pragma unroll
        for (int j = 0; j < 16; j++) {
            u64 w0, w1; lds_v2u64(w0, w1, &w1qs[j][l16]);
            u64 h = dup2(msx[w][nd][j]);
            fma2(zc0, w0, h); fma2(zc1, w1, h);
            u64 a0, a1; lds_v2u64(a0, a1, &w1qa[j][l16]);
            u64 ha = dup2(max_[w][nd][j]);
            fma2(za0, a0, ha); fma2(za1, a1, ha);
        }
        u64 zs0[4], zs1[4];
#pragma unroll
        for (int s = 0; s < 4; s++) { zs0[s] = zc0; zs1[s] = zc1; }
#pragma unroll
        for (int j = 0; j < 8; j++) {
            u64 w0, w1; lds_v2u64(w0, w1, &w1qs[16 + j][l16]);
#pragma unroll
            for (int s = 0; s < 4; s++) {
                u64 h = dup2(msc[w][nd][s][j]);
                fma2(zs0[s], w0, h); fma2(zs1[s], w1, h);
            }
            u64 a0, a1; lds_v2u64(a0, a1, &w1qa[16 + j][l16]);
            u64 ha = dup2(mac[w][nd][j]);
            fma2(za0, a0, ha); fma2(za1, a1, ha);
        }
#pragma unroll
        for (int s = 0; s < 4; s++) {
            float z0, z1, z2, z3;
            unpack2(zs0[s], z0, z1); unpack2(zs1[s], z2, z3);
            ss[0] += z0; ss[1] += z1; ss[2] += z2; ss[3] += z3;
            sq[0] += z0*z0; sq[1] += z1*z1; sq[2] += z2*z2; sq[3] += z3*z3;
        }
        {
            float z0, z1, z2, z3;
            unpack2(za0, z0, z1); unpack2(za1, z2, z3);
            as_[0] += z0; as_[1] += z1; as_[2] += z2; as_[3] += z3;
            aq[0] += z0*z0; aq[1] += z1*z1; aq[2] += z2*z2; aq[3] += z3*z3;
        }
    }
#pragma unroll
    for (int i = 0; i < 4; i++) {
        ss[i]  += __shfl_xor_sync(0xffffffffu, ss[i], 16);
        sq[i]  += __shfl_xor_sync(0xffffffffu, sq[i], 16);
        as_[i] += __shfl_xor_sync(0xffffffffu, as_[i], 16);
        aq[i]  += __shfl_xor_sync(0xffffffffu, aq[i], 16);
    }
    if (lane < 16) {
#pragma unroll
        for (int i = 0; i < 4; i++) {
            red[w][l16][i]      = ss[i];
            red[w][l16][4 + i]  = sq[i];
            red[w][l16][8 + i]  = as_[i];
            red[w][l16][12 + i] = aq[i];
        }
    }
    __syncthreads();
    {
        int l = tid >> 4, v = tid & 15;
        float acc = 0.f;
#pragma unroll
        for (int ww = 0; ww < 8; ww++) acc += red[ww][l][v];
        int col = 4 * l + (v & 3);
        if (v < 4)       atomicAdd(&g_s1[0][col], acc);
        else if (v < 8)  atomicAdd(&g_s2[0][col], acc);
        else if (v < 12) atomicAdd(&g_s1[1][col], acc);
        else             atomicAdd(&g_s2[1][col], acc);
    }
}

// ================= K3: compute BN alpha/beta =====================================
__global__ void k_fold(const float* __restrict__ g1s, const float* __restrict__ be1s,
                       const float* __restrict__ g1a, const float* __restrict__ be1a) {
    int t = threadIdx.x;
    if (t >= 128) return;
    int path = t >> 6, cc = t & 63;
    const float* g1 = path ? g1a : g1s;
    const float* be = path ? be1a : be1s;
    float invR = path ? (1.f / 50000.f) : (1.f / 200000.f);
    float mu  = g_s1[path][cc] * invR;
    float var = g_s2[path][cc] * invR - mu * mu;
    float alpha = g1[cc] * rsqrtf(var + 1e-5f);
    g_alpha[path][cc] = alpha;
    g_beta[path][cc]  = be[cc] - alpha * mu;
}

// ================= K4: aggregated-path MLP (8 nodes/warp) -> g_ma ================
__global__ void __launch_bounds__(256) k_agg(const float* __restrict__ x,
                                             const float* __restrict__ c,
                                             const float* __restrict__ W1a,
                                             const float* __restrict__ b1a,
                                             const float* __restrict__ W2a,
                                             const float* __restrict__ b2a,
                                             const float* __restrict__ eps_a_p) {
    __shared__ float4 w1q[24][16];
    __shared__ float4 w2q[64][16];
    __shared__ float rowa[8][8][24];
    __shared__ float hsa[8][8][64];
    int tid = threadIdx.x;
    for (int i = tid; i < 24 * 16; i += 256) {
        int j = i >> 4, l = i & 15;
        w1q[j][l] = *reinterpret_cast<const float4*>(&W1a[j * 64 + 4 * l]);
    }
    for (int i = tid; i < 64 * 16; i += 256) {
        int k = i >> 4, l = i & 15;
        w2q[k][l] = *reinterpret_cast<const float4*>(&W2a[k * 64 + 4 * l]);
    }
    float ea = 1.f + __ldg(eps_a_p);
    __syncthreads();
    int w = tid >> 5, lane = tid & 31, l16 = lane & 15, nd = lane >> 4;
    float4 b14 = __ldg(reinterpret_cast<const float4*>(b1a) + l16);
    float4 b24 = __ldg(reinterpret_cast<const float4*>(b2a) + l16);
    float4 al4 = *reinterpret_cast<const float4*>(&g_alpha[1][4 * l16]);
    float4 bt4 = *reinterpret_cast<const float4*>(&g_beta[1][4 * l16]);
    u64 b10 = pack2(b14.x, b14.y), b11 = pack2(b14.z, b14.w);
    u64 b20 = pack2(b24.x, b24.y), b21 = pack2(b24.z, b24.w);
    u64 au0 = pack2(al4.x, al4.y), au1 = pack2(al4.z, al4.w);
    u64 bu0 = pack2(bt4.x, bt4.y), bu1 = pack2(bt4.z, bt4.w);
    for (int p = blockIdx.x * 8 + w; p < 6250; p += gridDim.x * 8) {
        int nB = p * 8;
        __syncwarp();
#pragma unroll
        for (int it = 0; it < 6; it++) {
            int idx = lane + 32 * it;
            int node = idx / 24, j = idx % 24, n = nB + node;
            float v;
            if (j < 16) v = ea * x[n * 16 + j] + g_agg48[n * 48 + j];
            else {
                int j8 = j - 16;
                float csum = c[n*32 + j8] + c[n*32 + 8 + j8] + c[n*32 + 16 + j8] + c[n*32 + 24 + j8];
                float asum = g_agg48[n*48 + 16 + j8] + g_agg48[n*48 + 24 + j8]
                           + g_agg48[n*48 + 32 + j8] + g_agg48[n*48 + 40 + j8];
                v = 0.25f * (ea * csum + asum);
            }
            rowa[w][node][j] = v;
        }
        __syncwarp();
        u64 z0[4], z1[4];
#pragma unroll
        for (int i = 0; i < 4; i++) { z0[i] = b10; z1[i] = b11; }
#pragma unroll
        for (int j = 0; j < 24; j++) {
            u64 w0, w1; lds_v2u64(w0, w1, &w1q[j][l16]);
#pragma unroll
            for (int i = 0; i < 4; i++) {
                u64 h = dup2(rowa[w][nd * 4 + i][j]);
                fma2(z0[i], w0, h); fma2(z1[i], w1, h);
            }
        }
#pragma unroll
        for (int i = 0; i < 4; i++) {
            u64 t0 = bu0, t1 = bu1;
            fma2(t0, au0, z0[i]); fma2(t1, au1, z1[i]);
            float r0, r1, r2, r3;
            unpack2(t0, r0, r1); unpack2(t1, r2, r3);
            *reinterpret_cast<float4*>(&hsa[w][nd * 4 + i][4 * l16]) =
                make_float4(fmaxf(r0, 0.f), fmaxf(r1, 0.f), fmaxf(r2, 0.f), fmaxf(r3, 0.f));
        }
        __syncwarp();
        u64 o0[4], o1[4];
#pragma unroll
        for (int i = 0; i < 4; i++) { o0[i] = b20; o1[i] = b21; }
#pragma unroll
        for (int k = 0; k < 64; k++) {
            u64 w0, w1; lds_v2u64(w0, w1, &w2q[k][l16]);
#pragma unroll
            for (int i = 0; i < 4; i++) {
                u64 h = dup2(hsa[w][nd * 4 + i][k]);
                fma2(o0[i], w0, h); fma2(o1[i], w1, h);
            }
        }
#pragma unroll
        for (int i = 0; i < 4; i++) {
            int n = nB + nd * 4 + i;
            float r0, r1, r2, r3;
            unpack2(o0[i], r0, r1); unpack2(o1[i], r2, r3);
            *reinterpret_cast<float4*>(&g_ma[n * 64 + 4 * l16]) = make_float4(r0, r1, r2, r3);
        }
    }
}

// ================= K5: shared-path MLP (4 samples batched) + DSS -> out ==========
__global__ void __launch_bounds__(256) k_out(const float* __restrict__ x,
                                             const float* __restrict__ c,
                                             const float* __restrict__ W1s,
                                             const float* __restrict__ b1s,
                                             const float* __restrict__ W2s,
                                             const float* __restrict__ b2s,
                                             const float* __restrict__ eps_s_p,
                                             float* __restrict__ out) {
    __shared__ float4 w1q[24][16];
    __shared__ float4 w2q[64][16];
    __shared__ float msx[8][2][16], msc[8][2][4][8];
    __shared__ float hs[8][2][4][64];
    int tid = threadIdx.x;
    for (int i = tid; i < 24 * 16; i += 256) {
        int j = i >> 4, l = i & 15;
        w1q[j][l] = *reinterpret_cast<const float4*>(&W1s[j * 64 + 4 * l]);
    }
    for (int i = tid; i < 64 * 16; i += 256) {
        int k = i >> 4, l = i & 15;
        w2q[k][l] = *reinterpret_cast<const float4*>(&W2s[k * 64 + 4 * l]);
    }
    float es = 1.f + __ldg(eps_s_p);
    __syncthreads();
    int w = tid >> 5, lane = tid & 31, l16 = lane & 15, nd = lane >> 4;
    float4 b14 = __ldg(reinterpret_cast<const float4*>(b1s) + l16);
    float4 b24 = __ldg(reinterpret_cast<const float4*>(b2s) + l16);
    float4 al4 = *reinterpret_cast<const float4*>(&g_alpha[0][4 * l16]);
    float4 bt4 = *reinterpret_cast<const float4*>(&g_beta[0][4 * l16]);
    u64 b10 = pack2(b14.x, b14.y), b11 = pack2(b14.z, b14.w);
    u64 b20 = pack2(b24.x, b24.y), b21 = pack2(b24.z, b24.w);
    u64 au0 = pack2(al4.x, al4.y), au1 = pack2(al4.z, al4.w);
    u64 bu0 = pack2(bt4.x, bt4.y), bu1 = pack2(bt4.z, bt4.w);
    for (int p = blockIdx.x * 8 + w; p < 25000; p += gridDim.x * 8) {
        int nA = 2 * p;
        int n = nA + nd;
        __syncwarp();
#pragma unroll
        for (int it = 0; it < 3; it++) {
            int idx = lane + 32 * it;
            int node = idx / 48, r = idx % 48, nn = nA + node;
            if (r < 16) msx[w][node][r] = es * x[nn * 16 + r] + g_agg48[nn * 48 + r];
            else {
                int s = (r - 16) >> 3, j = (r - 16) & 7;
                msc[w][node][s][j] = es * c[nn * 32 + s * 8 + j]
                                   + g_agg48[nn * 48 + 16 + s * 8 + j];
            }
        }
        __syncwarp();
        u64 zc0 = b10, zc1 = b11;
#pragma unroll
        for (int j = 0; j < 16; j++) {
            u64 w0, w1; lds_v2u64(w0, w1, &w1q[j][l16]);
            u64 h = dup2(msx[w][nd][j]);
            fma2(zc0, w0, h); fma2(zc1, w1, h);
        }
        u64 zs0[4], zs1[4];
#pragma unroll
        for (int s = 0; s < 4; s++) { zs0[s] = zc0; zs1[s] = zc1; }
#pragma unroll
        for (int j = 0; j < 8; j++) {
            u64 w0, w1; lds_v2u64(w0, w1, &w1q[16 + j][l16]);
#pragma unroll
            for (int s = 0; s < 4; s++) {
                u64 h = dup2(msc[w][nd][s][j]);
                fma2(zs0[s], w0, h); fma2(zs1[s], w1, h);
            }
        }
#pragma unroll
        for (int s = 0; s < 4; s++) {
            u64 t0 = bu0, t1 = bu1;
            fma2(t0, au0, zs0[s]); fma2(t1, au1, zs1[s]);
            float r0, r1, r2, r3;
            unpack2(t0, r0, r1); unpack2(t1, r2, r3);
            *reinterpret_cast<float4*>(&hs[w][nd][s][4 * l16]) =
                make_float4(fmaxf(r0, 0.f), fmaxf(r1, 0.f), fmaxf(r2, 0.f), fmaxf(r3, 0.f));
        }
        float4 mav = *reinterpret_cast<const float4*>(&g_ma[n * 64 + 4 * l16]);
        __syncwarp();
        u64 o0[4], o1[4];
#pragma unroll
        for (int s = 0; s < 4; s++) { o0[s] = b20; o1[s] = b21; }
#pragma unroll
        for (int k = 0; k < 64; k++) {
            u64 w0, w1; lds_v2u64(w0, w1, &w2q[k][l16]);
#pragma unroll
            for (int s = 0; s < 4; s++) {
                u64 h = dup2(hs[w][nd][s][k]);
                fma2(o0[s], w0, h); fma2(o1[s], w1, h);
            }
        }
#pragma unroll
        for (int s = 0; s < 4; s++) {
            float r0, r1, r2, r3;
            unpack2(o0[s], r0, r1); unpack2(o1[s], r2, r3);
            *reinterpret_cast<float4*>(&out[n * 256 + s * 64 + 4 * l16]) =
                make_float4(r0 + mav.x, r1 + mav.y, r2 + mav.z, r3 + mav.w);
        }
    }
}

// ================= launch ========================================================
extern "C" void kernel_launch(void* const* d_in, const int* in_sizes, int n_in,
                              void* d_out, int out_size) {
    const float* x     = (const float*)d_in[0];
    const float* c     = (const float*)d_in[1];
    const int*   ei    = (const int*)  d_in[2];
    const float* eps_s = (const float*)d_in[3];
    const float* W1s   = (const float*)d_in[4];
    const float* b1s   = (const float*)d_in[5];
    const float* g1s   = (const float*)d_in[6];
    const float* be1s  = (const float*)d_in[7];
    const float* W2s   = (const float*)d_in[8];
    const float* b2s   = (const float*)d_in[9];
    const float* eps_a = (const float*)d_in[10];
    const float* W1a   = (const float*)d_in[11];
    const float* b1a   = (const float*)d_in[12];
    const float* g1a   = (const float*)d_in[13];
    const float* be1a  = (const float*)d_in[14];
    const float* W2a   = (const float*)d_in[15];
    const float* b2a   = (const float*)d_in[16];
    float* out = (float*)d_out;

    k_zeroA  <<<1172, 256>>>();
    k_zeroB  <<<1172, 256>>>();
    k_zeroC  <<<1, 128>>>();
    k_scatter<<<(N_EDGES * 4 + 255) / 256, 256>>>(ei, x, c);   // 4th launch -> profiled
    k_stats  <<<148, 256>>>(x, c, W1s, b1s, W1a, b1a, eps_s, eps_a);
    k_fold   <<<1, 128>>>(g1s, be1s, g1a, be1a);
    k_agg    <<<296, 256>>>(x, c, W1a, b1a, W2a, b2a, eps_a);
    k_out    <<<592, 256>>>(x, c, W1s, b1s, W2s, b2s, eps_s, out);
}